// round 12
// baseline (speedup 1.0000x reference)
#include <cuda_runtime.h>
#include <cuda_fp16.h>
#include <cstdint>

#define TILE 128
#define NT   256

// smem byte offsets. B tiles: 64 rows x 128 B, SW128 swizzle.
#define S_BH   0        // GEMM1 B hi (k-cols permuted)
#define S_BL   8192     // GEMM1 B lo*2048 (k-cols permuted)
#define S_RT   16384    // GEMM2 B = R^T hi (n-rows permuted)
#define S_CB   24576    // float[16]
#define S_BND  24640    // float[15] + pad
#define SMEM_BYTES 24704

#define INV2048 4.8828125e-4f

static __device__ __forceinline__ uint32_t smem_u32(const void* p) {
    uint32_t a;
    asm("{ .reg .u64 t; cvta.to.shared.u64 t, %1; cvt.u32.u64 %0, t; }" : "=r"(a) : "l"(p));
    return a;
}
// byte offset of fp16 (row, col) in a [*][64] fp16 tile with SW128 swizzle
static __device__ __forceinline__ int sw(int row, int col) {
    return row * 128 + ((col * 2) ^ ((row & 7) << 4));
}
// inverse of the fragment k-permutation pi (pi(j)= j<8 ? 4*(j>>1)+(j&1) : 4*((j-8)>>1)+2+(j&1))
static __device__ __forceinline__ int invperm(int s) {
    return ((s >> 2) << 1) | (s & 1) | ((s & 2) << 2);
}
static __device__ __forceinline__ uint32_t h2u(__half2 h) {
    return *reinterpret_cast<uint32_t*>(&h);
}
static __device__ __forceinline__ void ldsm4(uint32_t* r, uint32_t addr) {
    asm volatile("ldmatrix.sync.aligned.m8n8.x4.shared.b16 {%0,%1,%2,%3}, [%4];"
        : "=r"(r[0]), "=r"(r[1]), "=r"(r[2]), "=r"(r[3]) : "r"(addr));
}
static __device__ __forceinline__ void mma16816(float* c, const uint32_t* a,
                                                uint32_t b0, uint32_t b1) {
    asm volatile("mma.sync.aligned.m16n8k16.row.col.f32.f16.f16.f32 "
        "{%0,%1,%2,%3}, {%4,%5,%6,%7}, {%8,%9}, {%0,%1,%2,%3};"
        : "+f"(c[0]), "+f"(c[1]), "+f"(c[2]), "+f"(c[3])
        : "r"(a[0]), "r"(a[1]), "r"(a[2]), "r"(a[3]), "r"(b0), "r"(b1));
}

__global__ void __launch_bounds__(NT, 2)
tq_mma_kernel(const float* __restrict__ x, const float* __restrict__ cb,
              const float* __restrict__ Rg, float* __restrict__ out, int nrows)
{
    extern __shared__ char smem[];
    const uint32_t sb = smem_u32(smem);
    float* sCb  = (float*)(smem + S_CB);
    float* sBnd = (float*)(smem + S_BND);

    const int t   = threadIdx.x;
    const int wid = t >> 5;
    const int l   = t & 31;
    const int g   = l >> 2;      // fragment row group 0..7
    const int tq  = l & 3;       // fragment quad col
    const long long row0 = (long long)blockIdx.x * TILE;

    // ---- stage R with the fragment k-permutation baked in ----
    #pragma unroll 4
    for (int i = t; i < 4096; i += NT) {
        int j = i >> 6, k = i & 63;
        float v = Rg[i];
        __half hv = __float2half_rn(v);
        __half lv = __float2half_rn((v - __half2float(hv)) * 2048.0f);
        int kk = (k & ~15) | invperm(k & 15);
        *(__half*)(smem + S_BH + sw(j, kk)) = hv;    // GEMM1: n=j, k-col permuted
        *(__half*)(smem + S_BL + sw(j, kk)) = lv;
        *(__half*)(smem + S_RT + sw(kk, j)) = hv;    // GEMM2: n-row permuted, k-col=j
    }
    if (t < 16) sCb[t] = cb[t];
    if (t < 15) sBnd[t] = 0.5f * (cb[t] + cb[t + 1]);

    // ---- load x as float4s: rows rowA/rowA+8, cols 16ch+4tq..+3 ----
    const int rowA = wid * 16 + g;
    long long grow0 = row0 + rowA;
    long long grow1 = grow0 + 8;
    long long gr0 = grow0 < nrows ? grow0 : (long long)nrows - 1;
    long long gr1 = grow1 < nrows ? grow1 : (long long)nrows - 1;

    float4 v0[4], v1[4];
    float ss0 = 0.f, ss1 = 0.f;
    #pragma unroll
    for (int ch = 0; ch < 4; ch++) {
        v0[ch] = *(const float4*)(x + gr0 * 64 + 16 * ch + 4 * tq);
        v1[ch] = *(const float4*)(x + gr1 * 64 + 16 * ch + 4 * tq);
        ss0 += v0[ch].x*v0[ch].x + v0[ch].y*v0[ch].y + v0[ch].z*v0[ch].z + v0[ch].w*v0[ch].w;
        ss1 += v1[ch].x*v1[ch].x + v1[ch].y*v1[ch].y + v1[ch].z*v1[ch].z + v1[ch].w*v1[ch].w;
    }
    ss0 += __shfl_xor_sync(0xffffffffu, ss0, 1);
    ss0 += __shfl_xor_sync(0xffffffffu, ss0, 2);
    ss1 += __shfl_xor_sync(0xffffffffu, ss1, 1);
    ss1 += __shfl_xor_sync(0xffffffffu, ss1, 2);
    float scale0 = fmaxf(sqrtf(ss0), 1e-8f);
    float scale1 = fmaxf(sqrtf(ss1), 1e-8f);
    float inv0 = 1.0f / scale0;
    float inv1 = 1.0f / scale1;

    // split hi / scaled-lo; xh0[2ch]=cols(+0,+1) row g, xh0[2ch+1]=cols(+2,+3)
    uint32_t xh0[8], xl0[8], xh1[8], xl1[8];
    #pragma unroll
    for (int ch = 0; ch < 4; ch++) {
        float a0 = v0[ch].x*inv0, a1 = v0[ch].y*inv0, a2 = v0[ch].z*inv0, a3 = v0[ch].w*inv0;
        float b0 = v1[ch].x*inv1, b1 = v1[ch].y*inv1, b2 = v1[ch].z*inv1, b3 = v1[ch].w*inv1;
        __half2 hA = __floats2half2_rn(a0, a1), hB = __floats2half2_rn(a2, a3);
        __half2 hC = __floats2half2_rn(b0, b1), hD = __floats2half2_rn(b2, b3);
        float2 fA = __half22float2(hA), fB = __half22float2(hB);
        float2 fC = __half22float2(hC), fD = __half22float2(hD);
        xh0[2*ch]   = h2u(hA); xh0[2*ch+1] = h2u(hB);
        xh1[2*ch]   = h2u(hC); xh1[2*ch+1] = h2u(hD);
        xl0[2*ch]   = h2u(__floats2half2_rn((a0-fA.x)*2048.0f, (a1-fA.y)*2048.0f));
        xl0[2*ch+1] = h2u(__floats2half2_rn((a2-fB.x)*2048.0f, (a3-fB.y)*2048.0f));
        xl1[2*ch]   = h2u(__floats2half2_rn((b0-fC.x)*2048.0f, (b1-fC.y)*2048.0f));
        xl1[2*ch+1] = h2u(__floats2half2_rn((b2-fD.x)*2048.0f, (b3-fD.y)*2048.0f));
    }
    __syncthreads();   // B tiles + tables ready

    // quantizer tables: tree levels 1-3 in regs, level 4 + values via warp shuffle
    const float m1 = sBnd[1], m3 = sBnd[3], m5 = sBnd[5], m7 = sBnd[7];
    const float m9 = sBnd[9], m11 = sBnd[11], m13 = sBnd[13];
    const float bndv = sBnd[l & 15];   // lane-held boundary (lane 15 unused)
    const float cbv  = sCb[l & 15];

    // ---- LDSM lane addressing (shared by all three B tiles) ----
    const int tl  = l >> 3;
    const int rwi = l & 7;
    const int rsel = ((tl & 2) << 2) + rwi;
    const int cbyte = (tl & 1) << 4;
    const int swz = rwi << 4;
    int lo[4];
    #pragma unroll
    for (int ch = 0; ch < 4; ch++) lo[ch] = rsel * 128 + ((ch * 32 + cbyte) ^ swz);

    // ---- fused GEMM1 -> quantize -> GEMM2, one 16-col ntp block at a time ----
    float d[8][4];
    #pragma unroll
    for (int nt = 0; nt < 8; nt++)
        #pragma unroll
        for (int i = 0; i < 4; i++) d[nt][i] = 0.f;

    #pragma unroll
    for (int ntp = 0; ntp < 4; ntp++) {
        float c1[2][4], c2[2][4];
        #pragma unroll
        for (int s = 0; s < 2; s++)
            #pragma unroll
            for (int i = 0; i < 4; i++) { c1[s][i] = 0.f; c2[s][i] = 0.f; }

        #pragma unroll
        for (int ch = 0; ch < 4; ch++) {
            uint32_t bh[4], bl[4];
            ldsm4(bh, sb + S_BH + ntp * 2048 + lo[ch]);
            ldsm4(bl, sb + S_BL + ntp * 2048 + lo[ch]);
            uint32_t ah[4] = { xh0[2*ch], xh1[2*ch], xh0[2*ch+1], xh1[2*ch+1] };
            uint32_t al[4] = { xl0[2*ch], xl1[2*ch], xl0[2*ch+1], xl1[2*ch+1] };
            mma16816(c1[0], ah, bh[0], bh[1]);
            mma16816(c2[0], ah, bl[0], bl[1]);
            mma16816(c2[0], al, bh[0], bh[1]);
            mma16816(c1[1], ah, bh[2], bh[3]);
            mma16816(c2[1], ah, bl[2], bl[3]);
            mma16816(c2[1], al, bh[2], bh[3]);
        }

        // quantize this 16-col block (E = z_hat - z), shuffle-table lookup
        uint32_t ae[4];
        #pragma unroll
        for (int s = 0; s < 2; s++) {
            float e[4];
            #pragma unroll
            for (int i = 0; i < 4; i++) {
                float z = c1[s][i] + c2[s][i] * INV2048;
                bool cA = z > m7;
                float b2 = cA ? m11 : m3;
                bool cB = z > b2;
                float b3 = cA ? (cB ? m13 : m9) : (cB ? m5 : m1);
                bool cC = z > b3;
                int e8 = (cA ? 8 : 0) + (cB ? 4 : 0) + (cC ? 2 : 0);   // even idx 0..14
                float b4 = __shfl_sync(0xffffffffu, bndv, e8);
                int idx = e8 + ((z > b4) ? 1 : 0);
                float q = __shfl_sync(0xffffffffu, cbv, idx);
                e[i] = q - z;
            }
            ae[2*s]   = h2u(__floats2half2_rn(e[0], e[1]));
            ae[2*s+1] = h2u(__floats2half2_rn(e[2], e[3]));
        }

        #pragma unroll
        for (int ntp2 = 0; ntp2 < 4; ntp2++) {
            uint32_t br[4];
            ldsm4(br, sb + S_RT + ntp2 * 2048 + lo[ntp]);
            mma16816(d[2*ntp2],   ae, br[0], br[1]);
            mma16816(d[2*ntp2+1], ae, br[2], br[3]);
        }
    }

    // ---- epilogue: y = xn + E@R (cols re-aligned by the permutation), direct STG.128 ----
    #pragma unroll
    for (int ch = 0; ch < 4; ch++) {
        float2 hA = __half22float2(*reinterpret_cast<__half2*>(&xh0[2*ch]));
        float2 lA = __half22float2(*reinterpret_cast<__half2*>(&xl0[2*ch]));
        float2 hB = __half22float2(*reinterpret_cast<__half2*>(&xh0[2*ch+1]));
        float2 lB = __half22float2(*reinterpret_cast<__half2*>(&xl0[2*ch+1]));
        if (grow0 < nrows) {
            float4 o;
            o.x = (hA.x + lA.x * INV2048 + d[2*ch][0])   * scale0;
            o.y = (hA.y + lA.y * INV2048 + d[2*ch][1])   * scale0;
            o.z = (hB.x + lB.x * INV2048 + d[2*ch+1][0]) * scale0;
            o.w = (hB.y + lB.y * INV2048 + d[2*ch+1][1]) * scale0;
            *(float4*)(out + grow0 * 64 + 16 * ch + 4 * tq) = o;
        }
        float2 hC = __half22float2(*reinterpret_cast<__half2*>(&xh1[2*ch]));
        float2 lC = __half22float2(*reinterpret_cast<__half2*>(&xl1[2*ch]));
        float2 hD = __half22float2(*reinterpret_cast<__half2*>(&xh1[2*ch+1]));
        float2 lD = __half22float2(*reinterpret_cast<__half2*>(&xl1[2*ch+1]));
        if (grow1 < nrows) {
            float4 o;
            o.x = (hC.x + lC.x * INV2048 + d[2*ch][2])   * scale1;
            o.y = (hC.y + lC.y * INV2048 + d[2*ch][3])   * scale1;
            o.z = (hD.x + lD.x * INV2048 + d[2*ch+1][2]) * scale1;
            o.w = (hD.y + lD.y * INV2048 + d[2*ch+1][3]) * scale1;
            *(float4*)(out + grow1 * 64 + 16 * ch + 4 * tq) = o;
        }
    }
}

extern "C" void kernel_launch(void* const* d_in, const int* in_sizes, int n_in,
                              void* d_out, int out_size)
{
    const float* x  = (const float*)d_in[0];   // [2,32,4096,64] fp32
    const float* cb = (const float*)d_in[1];   // [16] fp32, sorted
    const float* Rg = (const float*)d_in[2];   // [64,64] fp32
    float* out = (float*)d_out;

    int nrows = in_sizes[0] / 64;
    int blocks = (nrows + TILE - 1) / TILE;

    tq_mma_kernel<<<blocks, NT, SMEM_BYTES>>>(x, cb, Rg, out, nrows);
}